// round 4
// baseline (speedup 1.0000x reference)
#include <cuda_runtime.h>

// CRF Viterbi decode: B=128, S=512, T=64.
// One CTA per batch, 64 threads; thread j owns tag j.
// Bit-exact FP association with reference: v = (f + trans[i][j]) + part[i].
// First-occurrence argmax: strict-> chains combined in ascending-i order.
// OUTPUT IS WRITTEN AS FLOAT32 VALUES (harness __output__ dtype is float).

#define BB 128
#define SS 512
#define TT 64
#define START_TAG 62
#define STOP_TAG 63
#define NEG_INF (-3.402823466e+38f)

__global__ __launch_bounds__(64, 1)
void crf_viterbi64(const float* __restrict__ feats,
                   const float* __restrict__ trans,
                   const unsigned* __restrict__ candA,
                   const unsigned* __restrict__ candB,
                   float* __restrict__ out)
{
    __shared__ float part[2][TT];
    __shared__ float lastp[TT];
    __shared__ unsigned char bp[SS][TT];   // bp[t][j] for t>=1, mask-applied
    __shared__ int s_len, s_ptr0, s_clsA, s_clsB;

    const int tid = threadIdx.x;   // tag index j
    const int b   = blockIdx.x;
    const int j   = tid;

    // diagnostic prefill: overwritten if the algorithm completes
    float* o = out + b * SS;
    for (int k = tid; k < SS; k += 64) o[k] = 63.0f;

    // ---- transitions column j into registers: tr[i] = trans[i][j]
    float tr[TT];
#pragma unroll
    for (int i = 0; i < TT; ++i) tr[i] = trans[i * TT + j];

    // ---- identify mask buffer + encoding by content -------------------------
    // bit0: words all in {0,1}            -> int32
    // bit1: words all in {0, 0x3F800000}  -> float32
    // bit2: bytes all in {0,1}            -> uint8
    // bit3: halves all in {0, 0x3F80}     -> bf16
    if (tid == 0) { s_len = 0; s_clsA = 0xF; s_clsB = 0xF; }
    __syncthreads();
    {
        int fa = 0xF, fbc = 0xF;
        for (int s = tid; s < 512; s += 64) {
            unsigned w = candA[s];
            if (w > 1u) fa &= ~1;
            if (w != 0u && w != 0x3F800000u) fa &= ~2;
            if (w & 0xFEFEFEFEu) fa &= ~4;
            { unsigned hi = w >> 16, lo = w & 0xFFFFu;
              if (!((hi==0u||hi==0x3F80u) && (lo==0u||lo==0x3F80u))) fa &= ~8; }
            w = candB[s];
            if (w > 1u) fbc &= ~1;
            if (w != 0u && w != 0x3F800000u) fbc &= ~2;
            if (w & 0xFEFEFEFEu) fbc &= ~4;
            { unsigned hi = w >> 16, lo = w & 0xFFFFu;
              if (!((hi==0u||hi==0x3F80u) && (lo==0u||lo==0x3F80u))) fbc &= ~8; }
        }
        atomicAnd(&s_clsA, fa);
        atomicAnd(&s_clsB, fbc);
    }
    __syncthreads();
    const unsigned* maskw = s_clsA ? candA : candB;
    const int cls = s_clsA ? s_clsA : (s_clsB ? s_clsB : 1);

    // ---- sequence length = nonzero count in mask row b ----------------------
    {
        int lsum = 0;
        if (cls & 3) {
            const unsigned* m = maskw + b * SS;
            for (int s = tid; s < SS; s += 64) lsum += (m[s] != 0u);
        } else if (cls & 4) {
            const unsigned char* m = (const unsigned char*)maskw + b * SS;
            for (int s = tid; s < SS; s += 64) lsum += (m[s] != 0);
        } else {
            const unsigned short* m = (const unsigned short*)maskw + b * SS;
            for (int s = tid; s < SS; s += 64) lsum += (m[s] != 0);
        }
        atomicAdd(&s_len, lsum);
    }

    // ---- part0 = feats[b,0,:] + transitions[START_TAG,:] --------------------
    const float* fb = feats + b * SS * TT;
    {
        float p0v = fb[j] + tr[START_TAG];
        part[0][j] = p0v;
        lastp[j]   = p0v;   // correct value if last_pos == 0 (history[0] = part0)
    }
    __syncthreads();
    int len = s_len;
    if (len < 1)  len = 1;
    if (len > SS) len = SS;
    const int last_pos = len - 1;

    // ---- forward recurrence (one barrier per step, double-buffered) ---------
    float fnext = fb[TT + j];
    int buf = 0;
#pragma unroll 1
    for (int t = 1; t < SS; ++t) {
        const float f = fnext;
        if (t + 1 < SS) fnext = fb[(t + 1) * TT + j];
        const float* p = part[buf];

        float b0 = NEG_INF, b1 = NEG_INF, b2 = NEG_INF, b3 = NEG_INF;
        int   a0 = 0,       a1 = 16,      a2 = 32,      a3 = 48;
#pragma unroll
        for (int u = 0; u < 16; ++u) {
            float v0 = (f + tr[u])      + p[u];
            float v1 = (f + tr[u + 16]) + p[u + 16];
            float v2 = (f + tr[u + 32]) + p[u + 32];
            float v3 = (f + tr[u + 48]) + p[u + 48];
            if (v0 > b0) { b0 = v0; a0 = u; }
            if (v1 > b1) { b1 = v1; a1 = u + 16; }
            if (v2 > b2) { b2 = v2; a2 = u + 32; }
            if (v3 > b3) { b3 = v3; a3 = u + 48; }
        }
        // combine ascending; strict > keeps the earliest index on ties
        if (b1 > b0) { b0 = b1; a0 = a1; }
        if (b3 > b2) { b2 = b3; a2 = a3; }
        if (b2 > b0) { b0 = b2; a0 = a2; }

        part[buf ^ 1][j] = b0;
        bp[t][j] = (unsigned char)((t < len) ? a0 : 0);
        if (t == last_pos) lastp[j] = b0;
        buf ^= 1;
        __syncthreads();
    }

    // ---- pointer0 = argmax_i( lastp[i] + trans[i][STOP_TAG] ) ---------------
    if (tid == STOP_TAG) {          // this thread's tr[i] == trans[i][STOP_TAG]
        float best = NEG_INF; int arg = 0;
#pragma unroll
        for (int i = 0; i < TT; ++i) {
            float v = lastp[i] + tr[i];
            if (v > best) { best = v; arg = i; }
        }
        s_ptr0 = arg;
    }
    __syncthreads();

    // ---- backtrack, output written as FLOAT values ---------------------------
    if (tid == 0) {
        const int p0 = s_ptr0;
        int ptr = p0;
        o[SS - 1] = (float)ptr;
        for (int k = SS - 2; k >= 0; --k) {
            ptr = (k == last_pos) ? p0 : (int)bp[k + 1][ptr];
            o[k] = (float)ptr;
        }
    }
}

extern "C" void kernel_launch(void* const* d_in, const int* in_sizes, int n_in,
                              void* d_out, int out_size) {
    // feats = largest buffer, transitions = smallest; the two leftovers are
    // {mask, tags}, disambiguated by content inside the kernel.
    int fi = 0, ti = 0;
    for (int i = 1; i < n_in; ++i) {
        if (in_sizes[i] > in_sizes[fi]) fi = i;
        if (in_sizes[i] < in_sizes[ti]) ti = i;
    }
    int cA = -1, cB = -1;
    for (int i = 0; i < n_in; ++i) {
        if (i == fi || i == ti) continue;
        if (cA < 0) cA = i; else if (cB < 0) cB = i;
    }
    if (cA < 0) cA = ti;
    if (cB < 0) cB = cA;

    crf_viterbi64<<<BB, 64>>>((const float*)d_in[fi],
                              (const float*)d_in[ti],
                              (const unsigned*)d_in[cA],
                              (const unsigned*)d_in[cB],
                              (float*)d_out);
}

// round 5
// speedup vs baseline: 1.2260x; 1.2260x over previous
#include <cuda_runtime.h>

// CRF Viterbi decode: B=128, S=512, T=64.
// One CTA per batch, 128 threads = 64 tags x 2 predecessor-segments
// (all 4 SMSPs busy). Bit-exact FP association with the reference:
// v = (f + trans[i][j]) + part[i]; first-occurrence argmax via strict->
// chains combined in ascending-i order. Output written as float32.

#define BB 128
#define SS 512
#define TT 64
#define START_TAG 62
#define STOP_TAG 63
#define NEG_INF (-3.402823466e+38f)

__global__ __launch_bounds__(128, 1)
void crf_viterbi128(const float* __restrict__ feats,
                    const float* __restrict__ trans,
                    const unsigned* __restrict__ candA,
                    const unsigned* __restrict__ candB,
                    float* __restrict__ out)
{
    __shared__ __align__(16) float part[2][TT];
    __shared__ float pbest[2][TT];
    __shared__ int   parg[2][TT];
    __shared__ float lastp[TT];
    __shared__ unsigned char bp[SS][TT];   // bp[t][j] for t>=1, mask-applied
    __shared__ int s_len, s_ptr0, s_clsA, s_clsB;

    const int tid = threadIdx.x;
    const int b   = blockIdx.x;
    const int j   = tid & (TT - 1);
    const int seg = tid >> 6;          // 0 or 1
    const int i0  = seg << 5;          // predecessor range [i0, i0+32)

    float* o = out + b * SS;

    // ---- transitions rows i0..i0+31 of column j into registers
    float tr[32];
#pragma unroll
    for (int u = 0; u < 32; ++u) tr[u] = trans[(i0 + u) * TT + j];

    // ---- identify mask buffer + encoding by content --------------------
    // bit0: words in {0,1} -> i32; bit1: {0,0x3F800000} -> f32;
    // bit2: bytes in {0,1} -> u8;  bit3: halves in {0,0x3F80} -> bf16
    if (tid == 0) { s_len = 0; s_clsA = 0xF; s_clsB = 0xF; }
    __syncthreads();
    {
        int fa = 0xF, fbc = 0xF;
        for (int s = tid; s < 512; s += 128) {
            unsigned w = candA[s];
            if (w > 1u) fa &= ~1;
            if (w != 0u && w != 0x3F800000u) fa &= ~2;
            if (w & 0xFEFEFEFEu) fa &= ~4;
            { unsigned hi = w >> 16, lo = w & 0xFFFFu;
              if (!((hi==0u||hi==0x3F80u) && (lo==0u||lo==0x3F80u))) fa &= ~8; }
            w = candB[s];
            if (w > 1u) fbc &= ~1;
            if (w != 0u && w != 0x3F800000u) fbc &= ~2;
            if (w & 0xFEFEFEFEu) fbc &= ~4;
            { unsigned hi = w >> 16, lo = w & 0xFFFFu;
              if (!((hi==0u||hi==0x3F80u) && (lo==0u||lo==0x3F80u))) fbc &= ~8; }
        }
        atomicAnd(&s_clsA, fa);
        atomicAnd(&s_clsB, fbc);
    }
    __syncthreads();
    const unsigned* maskw = s_clsA ? candA : candB;
    const int cls = s_clsA ? s_clsA : (s_clsB ? s_clsB : 1);

    // ---- sequence length = nonzero count in mask row b ------------------
    {
        int lsum = 0;
        if (cls & 3) {
            const unsigned* m = maskw + b * SS;
            for (int s = tid; s < SS; s += 128) lsum += (m[s] != 0u);
        } else if (cls & 4) {
            const unsigned char* m = (const unsigned char*)maskw + b * SS;
            for (int s = tid; s < SS; s += 128) lsum += (m[s] != 0);
        } else {
            const unsigned short* m = (const unsigned short*)maskw + b * SS;
            for (int s = tid; s < SS; s += 128) lsum += (m[s] != 0);
        }
        atomicAdd(&s_len, lsum);
    }

    // ---- part0 = feats[b,0,:] + transitions[START_TAG,:] ----------------
    const float* fb = feats + b * SS * TT;
    if (seg == 1) {                       // START_TAG=62 -> seg1, u=30
        float p0v = fb[j] + tr[30];
        part[0][j] = p0v;
        lastp[j]   = p0v;                 // correct when last_pos == 0
    }
    __syncthreads();
    int len = s_len;
    if (len < 1)  len = 1;
    if (len > SS) len = SS;
    const int last_pos = len - 1;

    // ---- forward recurrence (2 barriers per step) ------------------------
    float fnext = fb[TT + j];
    int buf = 0;
#pragma unroll 1
    for (int t = 1; t < SS; ++t) {
        const float f = fnext;
        if (t + 1 < SS) fnext = fb[(t + 1) * TT + j];

        // vectorized broadcast read of this segment's 32 partition values
        float pv[32];
        {
            const float4* p4 = (const float4*)(&part[buf][i0]);
#pragma unroll
            for (int q = 0; q < 8; ++q) {
                float4 v4 = p4[q];
                pv[4*q+0] = v4.x; pv[4*q+1] = v4.y;
                pv[4*q+2] = v4.z; pv[4*q+3] = v4.w;
            }
        }

        float b0 = NEG_INF, b1 = NEG_INF, b2 = NEG_INF, b3 = NEG_INF;
        int   a0 = 0,       a1 = 8,       a2 = 16,      a3 = 24;
#pragma unroll
        for (int u = 0; u < 8; ++u) {
            float v0 = (f + tr[u])      + pv[u];
            float v1 = (f + tr[u + 8])  + pv[u + 8];
            float v2 = (f + tr[u + 16]) + pv[u + 16];
            float v3 = (f + tr[u + 24]) + pv[u + 24];
            if (v0 > b0) { b0 = v0; a0 = u; }
            if (v1 > b1) { b1 = v1; a1 = u + 8; }
            if (v2 > b2) { b2 = v2; a2 = u + 16; }
            if (v3 > b3) { b3 = v3; a3 = u + 24; }
        }
        // combine ascending; strict > keeps the earliest index on ties
        if (b1 > b0) { b0 = b1; a0 = a1; }
        if (b3 > b2) { b2 = b3; a2 = a3; }
        if (b2 > b0) { b0 = b2; a0 = a2; }

        pbest[seg][j] = b0;
        parg[seg][j]  = i0 + a0;
        __syncthreads();

        if (seg == 0) {
            float best = b0;              // i0 == 0 for seg0
            int   arg  = a0;
            float bo = pbest[1][j];
            if (bo > best) { best = bo; arg = parg[1][j]; }
            part[buf ^ 1][j] = best;
            bp[t][j] = (unsigned char)((t < len) ? arg : 0);
            if (t == last_pos) lastp[j] = best;
        }
        buf ^= 1;
        __syncthreads();
    }

    // ---- pointer0 = argmax_i( lastp[i] + trans[i][STOP_TAG] ) ------------
    {
        float b0 = NEG_INF; int a0 = 0;
#pragma unroll
        for (int u = 0; u < 32; ++u) {
            float v = lastp[i0 + u] + tr[u];
            if (v > b0) { b0 = v; a0 = u; }
        }
        pbest[seg][j] = b0;
        parg[seg][j]  = i0 + a0;
        __syncthreads();
        if (tid == STOP_TAG) {            // seg0, column STOP_TAG
            float best = pbest[0][STOP_TAG];
            int   arg  = parg[0][STOP_TAG];
            if (pbest[1][STOP_TAG] > best) { arg = parg[1][STOP_TAG]; }
            s_ptr0 = arg;
        }
        __syncthreads();
    }

    // ---- backtrack, float output ------------------------------------------
    if (tid == 0) {
        const int p0 = s_ptr0;
        int ptr = p0;
        o[SS - 1] = (float)ptr;
        for (int k = SS - 2; k >= 0; --k) {
            ptr = (k == last_pos) ? p0 : (int)bp[k + 1][ptr];
            o[k] = (float)ptr;
        }
    }
}

extern "C" void kernel_launch(void* const* d_in, const int* in_sizes, int n_in,
                              void* d_out, int out_size) {
    // feats = largest buffer, transitions = smallest; the two leftovers are
    // {mask, tags}, disambiguated by content inside the kernel.
    int fi = 0, ti = 0;
    for (int i = 1; i < n_in; ++i) {
        if (in_sizes[i] > in_sizes[fi]) fi = i;
        if (in_sizes[i] < in_sizes[ti]) ti = i;
    }
    int cA = -1, cB = -1;
    for (int i = 0; i < n_in; ++i) {
        if (i == fi || i == ti) continue;
        if (cA < 0) cA = i; else if (cB < 0) cB = i;
    }
    if (cA < 0) cA = ti;
    if (cB < 0) cB = cA;

    crf_viterbi128<<<BB, 128>>>((const float*)d_in[fi],
                                (const float*)d_in[ti],
                                (const unsigned*)d_in[cA],
                                (const unsigned*)d_in[cB],
                                (float*)d_out);
}